// round 17
// baseline (speedup 1.0000x reference)
#include <cuda_runtime.h>
#include <cuda_fp16.h>
#include <cstdint>

// LocalGConv fp16 MMA, barrier-free: x loaded as MMA fragments directly from GMEM.
//   phase B (transposed): pre^T[o=16][v=48] = W_s^T @ x^T   (single fp16)
//   phase C (normal):     out[u=48][o=16] = adjcat @ pre    (single fp16)
// B=32768, V=43 (pad 48), DIN=DOUT=64, S=2.
// 512 threads = 16 warps = 4 groups; warps of a group track the same batch for
// L1 x-reuse but never synchronize. W-fragments hoisted; adj via ldsm from SMEM.

#define NT   512
#define GRID 1024
#define IT   8
#define NV   43

// SMEM word offsets
#define WT_OFF  0        // W^T fp16: [s*64+o rows][36 words]
#define ADJ_OFF 4608     // adj fp16: [48 u rows][52 words], k = s*48+v
#define SMEM_WORDS 7104
#define SMEM_BYTES (SMEM_WORDS * 4)   // 28,416 B

static __device__ __forceinline__ void mma16(float* d, const uint32_t* a, const uint32_t* b) {
    asm volatile(
        "mma.sync.aligned.m16n8k16.row.col.f32.f16.f16.f32 "
        "{%0,%1,%2,%3},{%4,%5,%6,%7},{%8,%9},{%0,%1,%2,%3};"
        : "+f"(d[0]), "+f"(d[1]), "+f"(d[2]), "+f"(d[3])
        : "r"(a[0]), "r"(a[1]), "r"(a[2]), "r"(a[3]), "r"(b[0]), "r"(b[1]));
}
static __device__ __forceinline__ void ldsm4(uint32_t* d, uint32_t addr) {
    asm volatile("ldmatrix.sync.aligned.m8n8.x4.shared.b16 {%0,%1,%2,%3}, [%4];"
        : "=r"(d[0]), "=r"(d[1]), "=r"(d[2]), "=r"(d[3]) : "r"(addr));
}
static __device__ __forceinline__ uint32_t su32(const void* p) {
    uint32_t a;
    asm("{ .reg .u64 t; cvta.to.shared.u64 t, %1; cvt.u32.u64 %0, t; }" : "=r"(a) : "l"(p));
    return a;
}
static __device__ __forceinline__ uint32_t f16x2(float hi, float lo) {
    uint32_t d;
    asm("cvt.rn.f16x2.f32 %0, %1, %2;" : "=r"(d) : "f"(hi), "f"(lo));
    return d;
}

__global__ __launch_bounds__(NT, 1)
void lgconv_fp16(const float* __restrict__ gx, const float* __restrict__ gadj,
                 const float* __restrict__ gw, const float* __restrict__ gb,
                 float* __restrict__ gout)
{
    extern __shared__ uint32_t sm[];
    uint16_t* shw = (uint16_t*)sm;
    const uint32_t sb = su32(sm);
    const int tid = threadIdx.x, wid = tid >> 5, lane = tid & 31;
    const int g = lane >> 2, t = lane & 3;
    const int grp = wid >> 2, wo = wid & 3;
    const int q = lane >> 3, rr = lane & 7;

    // ldmatrix per-lane byte offsets
    const uint32_t aoffW = (uint32_t)(((wo * 16 + (q & 1) * 8 + rr) * 36 + (q >> 1) * 4) * 4);
    const uint32_t aoffA = (uint32_t)((((q & 1) * 8 + rr) * 52 + (q >> 1) * 4) * 4);

    // ---- prologue: W^T fp16, adj fp16 (zero-padded) ----
    for (int i = tid; i < 2496; i += NT) sm[ADJ_OFF + i] = 0;
    for (int idx = tid; idx < 2 * 64 * 64; idx += NT) {
        int s = idx >> 12, i = (idx >> 6) & 63, o = idx & 63;
        __half hh = __float2half_rn(gw[idx]);
        shw[WT_OFF * 2 + (s * 64 + o) * 72 + i] = *(uint16_t*)&hh;
    }
    __syncthreads();
    for (int idx = tid; idx < 2 * NV * NV; idx += NT) {
        int s = idx / (NV * NV), r = idx % (NV * NV), u = r / NV, v = r % NV;
        __half h = __float2half_rn(gadj[idx]);
        shw[ADJ_OFF * 2 + u * 104 + s * 48 + v] = *(uint16_t*)&h;
    }
    float2 bb[2];
    #pragma unroll
    for (int oh = 0; oh < 2; ++oh)
        bb[oh] = *(const float2*)(gb + wo * 16 + oh * 8 + 2 * t);
    __syncthreads();

    const uint32_t wt_b  = sb + WT_OFF * 4;
    const uint32_t adj_b = sb + ADJ_OFF * 4;

    // ---- hoist W fragments: loop-invariant, loaded once ----
    uint32_t whf[4][2][4];
    #pragma unroll
    for (int kt = 0; kt < 4; ++kt)
        #pragma unroll
        for (int s = 0; s < 2; ++s)
            ldsm4(whf[kt][s], wt_b + (uint32_t)(s * 64 * 36 * 4) + kt * 32 + aoffW);

    // x-fragment row ownership (constant per lane): nb-th block row v = nb*8 + g? (g=lane>>2)
    // valid mask for pad rows v >= 43
    const int vrow = lane >> 2;               // 0..7 within block
    const int kcol = 2 * (lane & 3);          // 0,2,4,6
    const size_t bbase = (size_t)(blockIdx.x * 4 + grp) * IT;

    for (int it = 0; it < IT; ++it) {
        const size_t b = bbase + it;
        const float* xb = gx + b * (NV * 64);

        // ---- Phase B: pre^T[o][v] per support; x frags via direct LDG ----
        float accB[2][6][4];
        #pragma unroll
        for (int s = 0; s < 2; ++s)
            #pragma unroll
            for (int nt = 0; nt < 6; ++nt)
                #pragma unroll
                for (int j = 0; j < 4; ++j) accB[s][nt][j] = 0.f;

        float2 raw[12];
        // load kt = 0
        #pragma unroll
        for (int nb = 0; nb < 6; ++nb) {
            const int v = nb * 8 + vrow;
            const bool vok = v < NV;
            const float* xp = xb + v * 64 + kcol;
            raw[nb * 2]     = vok ? *(const float2*)(xp)     : make_float2(0.f, 0.f);
            raw[nb * 2 + 1] = vok ? *(const float2*)(xp + 8) : make_float2(0.f, 0.f);
        }

        #pragma unroll
        for (int kt = 0; kt < 4; ++kt) {
            // convert current raws to b-fragments
            uint32_t bf[12];
            #pragma unroll
            for (int j = 0; j < 12; ++j)
                bf[j] = f16x2(raw[j].y, raw[j].x);
            // issue next kt's loads (overwrite raw; independent of MMA below)
            if (kt < 3) {
                #pragma unroll
                for (int nb = 0; nb < 6; ++nb) {
                    const int v = nb * 8 + vrow;
                    const bool vok = v < NV;
                    const float* xp = xb + v * 64 + (kt + 1) * 16 + kcol;
                    raw[nb * 2]     = vok ? *(const float2*)(xp)     : make_float2(0.f, 0.f);
                    raw[nb * 2 + 1] = vok ? *(const float2*)(xp + 8) : make_float2(0.f, 0.f);
                }
            }
            #pragma unroll
            for (int s = 0; s < 2; ++s)
                #pragma unroll
                for (int nt = 0; nt < 6; ++nt)
                    mma16(accB[s][nt], whf[kt][s], &bf[nt * 2]);
        }

        // ---- pack accB -> phase-C B-fragments (registers only) ----
        uint32_t pb[2][3][2][2];   // [s][vb][oh][b0,b1]
        #pragma unroll
        for (int s = 0; s < 2; ++s)
            #pragma unroll
            for (int vb = 0; vb < 3; ++vb) {
                const float* c = accB[s][2 * vb];
                const float* d = accB[s][2 * vb + 1];
                pb[s][vb][0][0] = f16x2(c[1], c[0]);
                pb[s][vb][1][0] = f16x2(c[3], c[2]);
                pb[s][vb][0][1] = f16x2(d[1], d[0]);
                pb[s][vb][1][1] = f16x2(d[3], d[2]);
            }

        // ---- Phase C: out[u][own o] = bias + adjcat @ pre ----
        float oc[3][2][4];
        #pragma unroll
        for (int mt = 0; mt < 3; ++mt)
            #pragma unroll
            for (int oh = 0; oh < 2; ++oh) {
                oc[mt][oh][0] = bb[oh].x; oc[mt][oh][1] = bb[oh].y;
                oc[mt][oh][2] = bb[oh].x; oc[mt][oh][3] = bb[oh].y;
            }
        #pragma unroll
        for (int s = 0; s < 2; ++s)
            #pragma unroll
            for (int vb = 0; vb < 3; ++vb) {
                const uint32_t kb = (uint32_t)(s * 3 + vb) * 32;
                uint32_t ba[3][4];
                #pragma unroll
                for (int mt = 0; mt < 3; ++mt)
                    ldsm4(ba[mt], adj_b + (uint32_t)(mt * 16 * 52 * 4) + kb + aoffA);
                #pragma unroll
                for (int mt = 0; mt < 3; ++mt)
                    #pragma unroll
                    for (int oh = 0; oh < 2; ++oh)
                        mma16(oc[mt][oh], ba[mt], pb[s][vb][oh]);
            }

        // ---- epilogue: relu + coalesced float2 stores ----
        {
            float* op = gout + b * (NV * 64) + wo * 16 + 2 * t;
            #pragma unroll
            for (int mt = 0; mt < 3; ++mt)
                #pragma unroll
                for (int oh = 0; oh < 2; ++oh) {
                    const int u0 = mt * 16 + g, u1 = u0 + 8;
                    *(float2*)(op + u0 * 64 + oh * 8) =
                        make_float2(fmaxf(oc[mt][oh][0], 0.f), fmaxf(oc[mt][oh][1], 0.f));
                    if (u1 < NV)
                        *(float2*)(op + u1 * 64 + oh * 8) =
                            make_float2(fmaxf(oc[mt][oh][2], 0.f), fmaxf(oc[mt][oh][3], 0.f));
                }
        }
    }
}

extern "C" void kernel_launch(void* const* d_in, const int* in_sizes, int n_in,
                              void* d_out, int out_size) {
    const float* x   = (const float*)d_in[0];
    const float* adj = (const float*)d_in[1];
    const float* W   = (const float*)d_in[2];
    const float* b   = (const float*)d_in[3];
    float* out = (float*)d_out;

    cudaFuncSetAttribute(lgconv_fp16, cudaFuncAttributeMaxDynamicSharedMemorySize, SMEM_BYTES);
    lgconv_fp16<<<GRID, NT, SMEM_BYTES>>>(x, adj, W, b, out);
}